// round 16
// baseline (speedup 1.0000x reference)
#include <cuda_runtime.h>
#include <cuda_fp16.h>
#include <cstdint>

#define CIN 18
#define HH  256
#define WW  256
#define OCN 64
#define HWX 65536
#define NCHUNK 6          // 3 channels x 9 taps = 27 cols (+5 pad) = 32 cols per chunk

#define SMEM_A 0                     // 8 warps x 2 blocks x 8192 B = 131072
#define SMEM_B 131072                // 3 blocks x 8192 B = 24576
#define SMEM_TOTAL 155648

#define SW(o)  ((o) ^ (((o) >> 3) & 0x70))

__device__ __forceinline__ uint32_t smem_u32(const void* p) {
    uint32_t a;
    asm("{ .reg .u64 t; cvta.to.shared.u64 t, %1; cvt.u32.u64 %0, t; }" : "=r"(a) : "l"(p));
    return a;
}
__device__ __forceinline__ void sts128(uint4 v, uint32_t addr) {
    asm volatile("st.shared.v4.b32 [%0], {%1, %2, %3, %4};"
                 :: "r"(addr), "r"(v.x), "r"(v.y), "r"(v.z), "r"(v.w) : "memory");
}
__device__ __forceinline__ void sts32f(float v, uint32_t addr) {
    asm volatile("st.shared.f32 [%0], %1;" :: "r"(addr), "f"(v) : "memory");
}
__device__ __forceinline__ float4 lds128f(uint32_t addr) {
    float4 v;
    asm volatile("ld.shared.v4.f32 {%0, %1, %2, %3}, [%4];"
                 : "=f"(v.x), "=f"(v.y), "=f"(v.z), "=f"(v.w) : "r"(addr));
    return v;
}
__device__ __forceinline__ void ldmatrix_x4(uint32_t* r, uint32_t addr) {
    asm volatile("ldmatrix.sync.aligned.m8n8.x4.shared.b16 {%0, %1, %2, %3}, [%4];"
                 : "=r"(r[0]), "=r"(r[1]), "=r"(r[2]), "=r"(r[3]) : "r"(addr));
}
__device__ __forceinline__ void mma16816(float* d, const uint32_t* a, const uint32_t* b) {
    asm volatile("mma.sync.aligned.m16n8k16.row.col.f32.f16.f16.f32 "
                 "{%0, %1, %2, %3}, {%4, %5, %6, %7}, {%8, %9}, {%0, %1, %2, %3};"
                 : "+f"(d[0]), "+f"(d[1]), "+f"(d[2]), "+f"(d[3])
                 : "r"(a[0]), "r"(a[1]), "r"(a[2]), "r"(a[3]), "r"(b[0]), "r"(b[1]));
}

// Load one tap row for the warp's 64-px segment. Each thread loads only its
// own aligned float2; L/R halo comes from neighbor lanes via shfl. Lane 0/31
// handle the segment edge with a predicated scalar load (0 otherwise).
__device__ __forceinline__ void load_row(const float* r, bool rv, bool eL, bool eR,
                                         int lane, float* q) {
    float2 m = make_float2(0.f, 0.f);
    if (rv) m = *reinterpret_cast<const float2*>(r);
    float L = __shfl_up_sync(0xffffffffu, m.y, 1);
    float R = __shfl_down_sync(0xffffffffu, m.x, 1);
    if (lane == 0)  L = eL ? r[-1] : 0.f;
    if (lane == 31) R = eR ? r[2]  : 0.f;
    q[0] = L; q[1] = m.x; q[2] = m.y; q[3] = R;
}

__global__ __launch_bounds__(256)
void conv3x3_hmma9(const float* __restrict__ x,
                   const float* __restrict__ wgt,
                   const float* __restrict__ bias,
                   float* __restrict__ out) {
    extern __shared__ char smem[];
    const uint32_t sb   = smem_u32(smem);
    const int tid  = threadIdx.x;
    const int wid  = tid >> 5;
    const int lane = tid & 31;

    // ---- Build B once per CTA: chunk k -> block k>>1, column half (k&1)*64 B ----
    for (int i = tid; i < NCHUNK * 64; i += 256) {
        int chunk = i >> 6, oc = i & 63;
        __align__(16) __half cols[32];
        #pragma unroll
        for (int q = 27; q < 32; q++) cols[q] = __ushort_as_half(0);
        #pragma unroll
        for (int cl = 0; cl < 3; cl++) {
            int c = chunk * 3 + cl;
            #pragma unroll
            for (int t = 0; t < 9; t++)
                cols[cl * 9 + t] = __float2half_rn(wgt[oc * (CIN * 9) + c * 9 + t]);
        }
        const uint4* src = reinterpret_cast<const uint4*>(cols);
        uint32_t base = sb + SMEM_B + (chunk >> 1) * 8192;
        uint32_t co   = (chunk & 1) * 64;
        #pragma unroll
        for (int q = 0; q < 4; q++) {
            uint32_t off = (uint32_t)oc * 128 + co + q * 16;
            sts128(src[q], base + SW(off));
        }
    }
    __syncthreads();   // B ready; the ONLY CTA barrier

    // Warp geometry: strip = 2 image rows x 256 px. Warp owns 64 px of one row.
    const int wy = wid >> 2;
    const int Xw = (wid & 3) * 64;
    const int x0 = Xw + 2 * lane;
    const uint32_t abase0 = sb + SMEM_A + (uint32_t)wid * 16384;

    const bool lokE = (Xw > 0);               // lane-0 edge load valid
    const bool rokE = (Xw + 64 < WW);         // lane-31 edge load valid
    const int tsel = lane >> 3, rr = lane & 7;
    const int r0 = 2 * lane, r1 = 2 * lane + 1;

    #pragma unroll 1
    for (int si = 0; si < 4; si++) {
        const int s = blockIdx.x * 4 + si;
        const int n = s >> 7;
        const int y = ((s & 127) << 1) + wy;
        const float* xs = x + (long)n * CIN * HWX;
        const bool t0 = (y > 0);
        const bool t2 = (y < HH - 1);

        float q[3][3][4];
        // Prefetch chunk-0 taps (channels 0..2).
        #pragma unroll
        for (int cl = 0; cl < 3; cl++) {
            const float* base = xs + (long)cl * HWX;
            #pragma unroll
            for (int ky = 0; ky < 3; ky++) {
                bool rv = (ky == 0) ? t0 : (ky == 2) ? t2 : true;
                load_row(base + (long)(y + ky - 1) * WW + x0, rv,
                         rv && lokE, rv && rokE, lane, q[cl][ky]);
            }
        }

        float acc[4][8][4];
        #pragma unroll
        for (int mt = 0; mt < 4; mt++)
            #pragma unroll
            for (int nt = 0; nt < 8; nt++)
                #pragma unroll
                for (int qq = 0; qq < 4; qq++) acc[mt][nt][qq] = 0.0f;

        #pragma unroll 1
        for (int k = 0; k < NCHUNK; k++) {
            const uint32_t abuf = abase0 + (uint32_t)((k >> 1) & 1) * 8192;
            const uint32_t co   = (uint32_t)(k & 1) * 64;

            // ---- Build A (2 px rows, 3 channels, 1 fp16 col per tap) ----
            __half hh[3][3][4];
            #pragma unroll
            for (int cl = 0; cl < 3; cl++)
                #pragma unroll
                for (int ky = 0; ky < 3; ky++)
                    #pragma unroll
                    for (int j = 0; j < 4; j++)
                        hh[cl][ky][j] = __float2half_rn(q[cl][ky][j]);
            #pragma unroll
            for (int pxo = 0; pxo < 2; pxo++) {
                __align__(16) __half a[32];
                #pragma unroll
                for (int qq = 27; qq < 32; qq++) a[qq] = __ushort_as_half(0);
                #pragma unroll
                for (int cl = 0; cl < 3; cl++)
                    #pragma unroll
                    for (int ky = 0; ky < 3; ky++)
                        #pragma unroll
                        for (int kx = 0; kx < 3; kx++)
                            a[cl * 9 + ky * 3 + kx] = hh[cl][ky][kx + pxo];
                const uint4* src = reinterpret_cast<const uint4*>(a);
                uint32_t ro = (uint32_t)(pxo ? r1 : r0) * 128 + co;
                #pragma unroll
                for (int qi = 0; qi < 4; qi++)
                    sts128(src[qi], abuf + SW(ro + qi * 16));
            }
            __syncwarp();

            // Prefetch next chunk's taps (LDGs fly under the MMAs).
            if (k + 1 < NCHUNK) {
                #pragma unroll
                for (int cl = 0; cl < 3; cl++) {
                    const float* base = xs + (long)((k + 1) * 3 + cl) * HWX;
                    #pragma unroll
                    for (int ky = 0; ky < 3; ky++) {
                        bool rv = (ky == 0) ? t0 : (ky == 2) ? t2 : true;
                        load_row(base + (long)(y + ky - 1) * WW + x0, rv,
                                 rv && lokE, rv && rokE, lane, q[cl][ky]);
                    }
                }
            }

            // ---- MMA: warp tile 64 px x 64 oc, 2 k16 steps, A 1-ahead ----
            const uint32_t bb = sb + SMEM_B + (k >> 1) * 8192;
            #pragma unroll
            for (int st = 0; st < 2; st++) {
                uint32_t bfr[8][2];
                #pragma unroll
                for (int p = 0; p < 4; p++) {
                    int row = p * 16 + (tsel >> 1) * 8 + rr;
                    uint32_t off = (uint32_t)row * 128 + co + st * 32 + (tsel & 1) * 16;
                    uint32_t m[4];
                    ldmatrix_x4(m, bb + SW(off));
                    bfr[2 * p][0]     = m[0];
                    bfr[2 * p][1]     = m[1];
                    bfr[2 * p + 1][0] = m[2];
                    bfr[2 * p + 1][1] = m[3];
                }
                uint32_t afr[2][4];
                {
                    int row = (tsel & 1) * 8 + rr;
                    uint32_t off = (uint32_t)row * 128 + co + st * 32 + (tsel >> 1) * 16;
                    ldmatrix_x4(afr[0], abuf + SW(off));
                }
                #pragma unroll
                for (int mt = 0; mt < 4; mt++) {
                    if (mt < 3) {
                        int row = (mt + 1) * 16 + (tsel & 1) * 8 + rr;
                        uint32_t off = (uint32_t)row * 128 + co + st * 32 + (tsel >> 1) * 16;
                        ldmatrix_x4(afr[(mt + 1) & 1], abuf + SW(off));
                    }
                    const uint32_t* af = afr[mt & 1];
                    #pragma unroll
                    for (int nt = 0; nt < 8; nt++)
                        mma16816(acc[mt][nt], af, bfr[nt]);
                }
            }
        }

        // ---- Epilogue: transpose through warp-private smem, coalesced STG.128 ----
        float* ob = out + ((long)n * OCN) * HWX + (long)y * WW + Xw;
        const uint32_t tb = abase0;
        #pragma unroll
        for (int pass = 0; pass < 4; pass++) {
            __syncwarp();   // previous pass's LDS done before overwrite
            #pragma unroll
            for (int t = 0; t < 2; t++) {
                const int nt  = pass * 2 + t;
                const int ocl = t * 8 + (lane & 3) * 2;
                const int ocg = pass * 16 + ocl;
                const float b0 = bias[ocg], b1 = bias[ocg + 1];
                const uint32_t a0 = tb + (uint32_t)ocl * 272;
                const uint32_t a1 = a0 + 272;
                #pragma unroll
                for (int mt = 0; mt < 4; mt++) {
                    const int rl = mt * 16 + (lane >> 2);
                    sts32f(acc[mt][nt][0] + b0, a0 + rl * 4);
                    sts32f(acc[mt][nt][1] + b1, a1 + rl * 4);
                    sts32f(acc[mt][nt][2] + b0, a0 + (rl + 8) * 4);
                    sts32f(acc[mt][nt][3] + b1, a1 + (rl + 8) * 4);
                }
            }
            __syncwarp();
            #pragma unroll
            for (int j = 0; j < 8; j++) {
                const int idx  = j * 32 + lane;
                const int ocl  = idx >> 4;
                const int quad = idx & 15;
                float4 v = lds128f(tb + (uint32_t)ocl * 272 + quad * 16);
                float* p = ob + (long)(pass * 16 + ocl) * HWX + quad * 4;
                *reinterpret_cast<float4*>(p) = v;
            }
        }
        __syncwarp();   // epilogue reads done before next strip's A build
    }
}

extern "C" void kernel_launch(void* const* d_in, const int* in_sizes, int n_in,
                              void* d_out, int out_size) {
    const float* x    = (const float*)d_in[0];
    const float* wgt  = (const float*)d_in[1];
    const float* bias = (const float*)d_in[2];
    float* out        = (float*)d_out;

    cudaFuncSetAttribute(conv3x3_hmma9, cudaFuncAttributeMaxDynamicSharedMemorySize, SMEM_TOTAL);
    conv3x3_hmma9<<<1024, 256, SMEM_TOTAL>>>(x, wgt, bias, out);
}

// round 17
// speedup vs baseline: 1.1744x; 1.1744x over previous
#include <cuda_runtime.h>
#include <cuda_fp16.h>
#include <cstdint>

#define CIN 18
#define HH  256
#define WW  256
#define OCN 64
#define HWX 65536
#define NCHUNK 6          // 3 channels x 9 taps = 27 cols (+5 pad) = 32 cols per chunk

#define SMEM_A 0                     // 8 warps x 2 blocks x 8192 B = 131072
#define SMEM_B 131072                // 3 blocks x 8192 B = 24576
#define SMEM_TOTAL 155648

#define SW(o)  ((o) ^ (((o) >> 3) & 0x70))

__device__ __forceinline__ uint32_t smem_u32(const void* p) {
    uint32_t a;
    asm("{ .reg .u64 t; cvta.to.shared.u64 t, %1; cvt.u32.u64 %0, t; }" : "=r"(a) : "l"(p));
    return a;
}
__device__ __forceinline__ void sts128(uint4 v, uint32_t addr) {
    asm volatile("st.shared.v4.b32 [%0], {%1, %2, %3, %4};"
                 :: "r"(addr), "r"(v.x), "r"(v.y), "r"(v.z), "r"(v.w) : "memory");
}
__device__ __forceinline__ void sts32f(float v, uint32_t addr) {
    asm volatile("st.shared.f32 [%0], %1;" :: "r"(addr), "f"(v) : "memory");
}
__device__ __forceinline__ float4 lds128f(uint32_t addr) {
    float4 v;
    asm volatile("ld.shared.v4.f32 {%0, %1, %2, %3}, [%4];"
                 : "=f"(v.x), "=f"(v.y), "=f"(v.z), "=f"(v.w) : "r"(addr));
    return v;
}
__device__ __forceinline__ void ldmatrix_x4(uint32_t* r, uint32_t addr) {
    asm volatile("ldmatrix.sync.aligned.m8n8.x4.shared.b16 {%0, %1, %2, %3}, [%4];"
                 : "=r"(r[0]), "=r"(r[1]), "=r"(r[2]), "=r"(r[3]) : "r"(addr));
}
__device__ __forceinline__ void mma16816(float* d, const uint32_t* a, const uint32_t* b) {
    asm volatile("mma.sync.aligned.m16n8k16.row.col.f32.f16.f16.f32 "
                 "{%0, %1, %2, %3}, {%4, %5, %6, %7}, {%8, %9}, {%0, %1, %2, %3};"
                 : "+f"(d[0]), "+f"(d[1]), "+f"(d[2]), "+f"(d[3])
                 : "r"(a[0]), "r"(a[1]), "r"(a[2]), "r"(a[3]), "r"(b[0]), "r"(b[1]));
}
// Two floats -> packed half2 in one F2FP instruction.
__device__ __forceinline__ uint32_t f2h2(float lo, float hi) {
    uint32_t r;
    asm("cvt.rn.f16x2.f32 %0, %1, %2;" : "=r"(r) : "f"(hi), "f"(lo));
    return r;
}

__global__ __launch_bounds__(256)
void conv3x3_hmma10(const float* __restrict__ x,
                    const float* __restrict__ wgt,
                    const float* __restrict__ bias,
                    float* __restrict__ out) {
    extern __shared__ char smem[];
    const uint32_t sb   = smem_u32(smem);
    const int tid  = threadIdx.x;
    const int wid  = tid >> 5;
    const int lane = tid & 31;

    // ---- Build B once per CTA: chunk k -> block k>>1, column half (k&1)*64 B ----
    for (int i = tid; i < NCHUNK * 64; i += 256) {
        int chunk = i >> 6, oc = i & 63;
        __align__(16) __half cols[32];
        #pragma unroll
        for (int q = 27; q < 32; q++) cols[q] = __ushort_as_half(0);
        #pragma unroll
        for (int cl = 0; cl < 3; cl++) {
            int c = chunk * 3 + cl;
            #pragma unroll
            for (int t = 0; t < 9; t++)
                cols[cl * 9 + t] = __float2half_rn(wgt[oc * (CIN * 9) + c * 9 + t]);
        }
        const uint4* src = reinterpret_cast<const uint4*>(cols);
        uint32_t base = sb + SMEM_B + (chunk >> 1) * 8192;
        uint32_t co   = (chunk & 1) * 64;
        #pragma unroll
        for (int q = 0; q < 4; q++) {
            uint32_t off = (uint32_t)oc * 128 + co + q * 16;
            sts128(src[q], base + SW(off));
        }
    }
    __syncthreads();   // B ready; the ONLY CTA barrier

    // Warp geometry: strip = 2 image rows x 256 px. Warp owns 64 px of one row.
    const int wy = wid >> 2;
    const int Xw = (wid & 3) * 64;
    const int x0 = Xw + 2 * lane;
    const uint32_t abase0 = sb + SMEM_A + (uint32_t)wid * 16384;

    const bool lok = (x0 > 0);
    const bool rok = (x0 + 2 < WW);
    const int tsel = lane >> 3, rr = lane & 7;
    const int r0 = 2 * lane, r1 = 2 * lane + 1;

    #pragma unroll 1
    for (int si = 0; si < 4; si++) {
        const int s = blockIdx.x * 4 + si;
        const int n = s >> 7;
        const int y = ((s & 127) << 1) + wy;
        const float* xs = x + (long)n * CIN * HWX;
        const bool t0 = (y > 0);
        const bool t2 = (y < HH - 1);

        float q[3][3][4];
        // Prefetch chunk-0 taps (channels 0..2) into float regs (pure LDGs).
        #pragma unroll
        for (int cl = 0; cl < 3; cl++) {
            const float* base = xs + (long)cl * HWX;
            #pragma unroll
            for (int ky = 0; ky < 3; ky++) {
                bool rv = (ky == 0) ? t0 : (ky == 2) ? t2 : true;
                const float* r = base + (long)(y + ky - 1) * WW + x0;
                if (rv) {
                    q[cl][ky][0] = lok ? r[-1] : 0.0f;
                    float2 m = *reinterpret_cast<const float2*>(r);
                    q[cl][ky][1] = m.x; q[cl][ky][2] = m.y;
                    q[cl][ky][3] = rok ? r[2] : 0.0f;
                } else {
                    q[cl][ky][0] = q[cl][ky][1] = q[cl][ky][2] = q[cl][ky][3] = 0.0f;
                }
            }
        }

        float acc[4][8][4];
        #pragma unroll
        for (int mt = 0; mt < 4; mt++)
            #pragma unroll
            for (int nt = 0; nt < 8; nt++)
                #pragma unroll
                for (int qq = 0; qq < 4; qq++) acc[mt][nt][qq] = 0.0f;

        #pragma unroll 1
        for (int k = 0; k < NCHUNK; k++) {
            const uint32_t abuf = abase0 + (uint32_t)((k >> 1) & 1) * 8192;
            const uint32_t co   = (uint32_t)(k & 1) * 64;

            // ---- Build A: direct F2FP packing, 16 half2 words per px row ----
            #pragma unroll
            for (int pxo = 0; pxo < 2; pxo++) {
                uint32_t a2[16];
                #pragma unroll
                for (int j = 0; j < 13; j++) {         // cols 2j, 2j+1 (0..25)
                    const int c0 = 2 * j,     cl0 = c0 / 9, ky0 = (c0 % 9) / 3, kx0 = c0 % 3;
                    const int c1 = 2 * j + 1, cl1 = c1 / 9, ky1 = (c1 % 9) / 3, kx1 = c1 % 3;
                    a2[j] = f2h2(q[cl0][ky0][kx0 + pxo], q[cl1][ky1][kx1 + pxo]);
                }
                a2[13] = f2h2(q[2][2][2 + pxo], 0.0f);  // col 26 + pad
                a2[14] = 0u;
                a2[15] = 0u;
                uint32_t ro = (uint32_t)(pxo ? r1 : r0) * 128 + co;
                #pragma unroll
                for (int qi = 0; qi < 4; qi++) {
                    uint4 v = make_uint4(a2[4 * qi], a2[4 * qi + 1],
                                         a2[4 * qi + 2], a2[4 * qi + 3]);
                    sts128(v, abuf + SW(ro + qi * 16));
                }
            }
            __syncwarp();

            // Prefetch next chunk's taps (pure LDGs; fly under the MMAs).
            if (k + 1 < NCHUNK) {
                #pragma unroll
                for (int cl = 0; cl < 3; cl++) {
                    const float* base = xs + (long)((k + 1) * 3 + cl) * HWX;
                    #pragma unroll
                    for (int ky = 0; ky < 3; ky++) {
                        bool rv = (ky == 0) ? t0 : (ky == 2) ? t2 : true;
                        const float* r = base + (long)(y + ky - 1) * WW + x0;
                        if (rv) {
                            q[cl][ky][0] = lok ? r[-1] : 0.0f;
                            float2 m = *reinterpret_cast<const float2*>(r);
                            q[cl][ky][1] = m.x; q[cl][ky][2] = m.y;
                            q[cl][ky][3] = rok ? r[2] : 0.0f;
                        } else {
                            q[cl][ky][0] = q[cl][ky][1] = q[cl][ky][2] = q[cl][ky][3] = 0.0f;
                        }
                    }
                }
            }

            // ---- MMA: warp tile 64 px x 64 oc, 2 k16 steps ----
            const uint32_t bb = sb + SMEM_B + (k >> 1) * 8192;
            #pragma unroll
            for (int st = 0; st < 2; st++) {
                uint32_t bfr[8][2];
                #pragma unroll
                for (int p = 0; p < 4; p++) {
                    int row = p * 16 + (tsel >> 1) * 8 + rr;
                    uint32_t off = (uint32_t)row * 128 + co + st * 32 + (tsel & 1) * 16;
                    uint32_t m[4];
                    ldmatrix_x4(m, bb + SW(off));
                    bfr[2 * p][0]     = m[0];
                    bfr[2 * p][1]     = m[1];
                    bfr[2 * p + 1][0] = m[2];
                    bfr[2 * p + 1][1] = m[3];
                }
                #pragma unroll
                for (int mt = 0; mt < 4; mt++) {
                    uint32_t afr[4];
                    int row = mt * 16 + (tsel & 1) * 8 + rr;
                    uint32_t off = (uint32_t)row * 128 + co + st * 32 + (tsel >> 1) * 16;
                    ldmatrix_x4(afr, abuf + SW(off));
                    #pragma unroll
                    for (int nt = 0; nt < 8; nt++)
                        mma16816(acc[mt][nt], afr, bfr[nt]);
                }
            }
        }

        // ---- Epilogue: transpose through warp-private smem, coalesced STG.128 ----
        float* ob = out + ((long)n * OCN) * HWX + (long)y * WW + Xw;
        const uint32_t tb = abase0;
        #pragma unroll
        for (int pass = 0; pass < 4; pass++) {
            __syncwarp();   // previous pass's LDS done before overwrite
            #pragma unroll
            for (int t = 0; t < 2; t++) {
                const int nt  = pass * 2 + t;
                const int ocl = t * 8 + (lane & 3) * 2;
                const int ocg = pass * 16 + ocl;
                const float b0 = bias[ocg], b1 = bias[ocg + 1];
                const uint32_t a0 = tb + (uint32_t)ocl * 272;
                const uint32_t a1 = a0 + 272;
                #pragma unroll
                for (int mt = 0; mt < 4; mt++) {
                    const int rl = mt * 16 + (lane >> 2);
                    sts32f(acc[mt][nt][0] + b0, a0 + rl * 4);
                    sts32f(acc[mt][nt][1] + b1, a1 + rl * 4);
                    sts32f(acc[mt][nt][2] + b0, a0 + (rl + 8) * 4);
                    sts32f(acc[mt][nt][3] + b1, a1 + (rl + 8) * 4);
                }
            }
            __syncwarp();
            #pragma unroll
            for (int j = 0; j < 8; j++) {
                const int idx  = j * 32 + lane;
                const int ocl  = idx >> 4;
                const int quad = idx & 15;
                float4 v = lds128f(tb + (uint32_t)ocl * 272 + quad * 16);
                float* p = ob + (long)(pass * 16 + ocl) * HWX + quad * 4;
                *reinterpret_cast<float4*>(p) = v;
            }
        }
        __syncwarp();   // epilogue reads done before next strip's A build
    }
}

extern "C" void kernel_launch(void* const* d_in, const int* in_sizes, int n_in,
                              void* d_out, int out_size) {
    const float* x    = (const float*)d_in[0];
    const float* wgt  = (const float*)d_in[1];
    const float* bias = (const float*)d_in[2];
    float* out        = (float*)d_out;

    cudaFuncSetAttribute(conv3x3_hmma10, cudaFuncAttributeMaxDynamicSharedMemorySize, SMEM_TOTAL);
    conv3x3_hmma10<<<1024, 256, SMEM_TOTAL>>>(x, wgt, bias, out);
}